// round 16
// baseline (speedup 1.0000x reference)
#include <cuda_runtime.h>
#include <cuda_bf16.h>
#include <math.h>

#define BATCH 8
#define CT 16
#define LEN 2048
#define NDB 2048
#define NSEG 31
#define NPS 128
#define STEP 64
#define NF 65
#define TABW 66            // table row stride in float2 (16B-aligned rows)
#define TOPK 32
#define TN 2               // DB rows per k_scores block (fused in one t-loop)
#define EPSV 1e-12f
#define PI_D 3.14159265358979323846264338327950288

typedef unsigned long long ull;
typedef unsigned int uint32;

#define FMA2(acc, a, b) asm("fma.rn.f32x2 %0, %1, %2, %0;" : "+l"(acc) : "l"(a), "l"(b))
#define UNPACK2(lo, hi, src) asm("mov.b64 {%0,%1}, %2;" : "=r"(lo), "=r"(hi) : "l"(src))

// ---------------- scratch (__device__ globals; no allocation allowed) ------
__device__ float2 g_tab[NF * TABW];                // [t*TABW+f]: {w*cos, -w*sin}
__device__ float2 g_X[BATCH * CT * NSEG * NF];     // target spectra
__device__ float  g_Pxx[BATCH * CT * NF];
__device__ float  g_scores[BATCH * CT * NDB];
__device__ int    g_sidx[BATCH * CT * TOPK];

// ---------------- kernel 0: half twiddle table (Hann folded, double prec) --
__global__ void k_table() {
    int i = blockIdx.x * blockDim.x + threadIdx.x;
    if (i < NF * TABW) {
        int t = i / TABW, f = i % TABW;
        if (f < NF) {
            double w = 0.5 - 0.5 * cos(2.0 * PI_D * (double)t / (double)NPS);
            double ang = 2.0 * PI_D * (double)f * (double)t / (double)NPS;
            float ws = (t == 0 || t == 64) ? 0.f : (float)(-w * sin(ang));
            g_tab[i] = make_float2((float)(w * cos(ang)), ws);
        } else {
            g_tab[i] = make_float2(0.f, 0.f);
        }
    }
}

// ---------------- kernel 1: X spectra + Pxx (one block per (b,c)) ----------
__global__ __launch_bounds__(256) void k_xspec(const float* __restrict__ tgt) {
    int bc = blockIdx.x;
    int tid = threadIdx.x;
    __shared__ float sx[2176];
    __shared__ float smu[32];
    __shared__ float2 sY[NSEG * NF];

    const float* src = tgt + (size_t)bc * LEN;
    for (int i = tid; i < LEN; i += 256) sx[i] = src[i];
    for (int i = LEN + tid; i < 2176; i += 256) sx[i] = 0.f;
    __syncthreads();
    if (tid < 32) {
        float acc = 0.f;
        if (tid < NSEG) {
            const float* p = &sx[tid * STEP];
            for (int t = 0; t < NPS; t++) acc += p[t];
        }
        smu[tid] = acc * (1.f / NPS);
    }
    __syncthreads();
    for (int o = tid; o < NSEG * NF; o += 256) {
        int s = o / NF, f = o % NF;
        const float* fr = &sx[s * STEP];
        float mu = smu[s];
        float ar = 0.f, ai = 0.f;
        {
            float v0 = fr[0] - mu;
            float2 tb = g_tab[f];                 // t=0
            ar = fmaf(v0, tb.x, ar);
        }
        for (int t = 1; t < 64; t++) {
            float a = (fr[t] - mu) + (fr[128 - t] - mu);
            float d = fr[t] - fr[128 - t];
            float2 tb = g_tab[t * TABW + f];
            ar = fmaf(a, tb.x, ar);
            ai = fmaf(d, tb.y, ai);
        }
        {
            float v64 = fr[64] - mu;
            float2 tb = g_tab[64 * TABW + f];
            ar = fmaf(v64, tb.x, ar);
        }
        sY[o] = make_float2(ar, ai);
        g_X[(size_t)bc * (NSEG * NF) + o] = make_float2(ar, ai);
    }
    __syncthreads();
    if (tid < NF) {
        float acc = 0.f;
        for (int s = 0; s < NSEG; s++) {
            float2 y = sY[s * NF + tid];
            acc = fmaf(y.x, y.x, fmaf(y.y, y.y, acc));
        }
        g_Pxx[bc * NF + tid] = acc * (1.f / NSEG);
    }
}

// one t-step of the fused 2-row DFT (8 freqs + optional f=64)
#define DFT_STEP(tt, adAa, adBb)                                              \
    do {                                                                      \
        const ulonglong2* tq = (const ulonglong2*)&sTab[(tt) * TABW + f0];    \
        ulonglong2 q0 = tq[0];                                                \
        ulonglong2 q1 = tq[1];                                                \
        ulonglong2 q2 = tq[2];                                                \
        ulonglong2 q3 = tq[3];                                                \
        FMA2(accA[0], adAa, q0.x); FMA2(accB[0], adBb, q0.x);                 \
        FMA2(accA[1], adAa, q0.y); FMA2(accB[1], adBb, q0.y);                 \
        FMA2(accA[2], adAa, q1.x); FMA2(accB[2], adBb, q1.x);                 \
        FMA2(accA[3], adAa, q1.y); FMA2(accB[3], adBb, q1.y);                 \
        FMA2(accA[4], adAa, q2.x); FMA2(accB[4], adBb, q2.x);                 \
        FMA2(accA[5], adAa, q2.y); FMA2(accB[5], adBb, q2.y);                 \
        FMA2(accA[6], adAa, q3.x); FMA2(accB[6], adBb, q3.x);                 \
        FMA2(accA[7], adAa, q3.y); FMA2(accB[7], adBb, q3.y);                 \
        if (w == 0) {                                                         \
            ull t64 = *(const ull*)&sTab[(tt) * TABW + 64];                   \
            FMA2(accA64, adAa, t64);                                          \
            FMA2(accB64, adBb, t64);                                          \
        }                                                                     \
    } while (0)

// ---------------- kernel 2: scores (one block per TN=2 DB rows) ------------
// R15 structure; fold output packed as float4 (A,D @ t, A,D @ t+1) with
// per-segment stride 33 float4 (conflict-free LDS.128) so one 128-bit load
// feeds two t-steps per row. All accumulation chains byte-identical to R15.
__global__ __launch_bounds__(256, 2) void k_scores(const float* __restrict__ db,
                                                   int blk_base) {
    int blk = blk_base + blockIdx.x;           // b * (NDB/TN) + ntile
    int b = blk / (NDB / TN);
    int n0 = (blk % (NDB / TN)) * TN;
    int tid = threadIdx.x;

    __shared__ float2 sTab[NF * TABW];         // 34320 B; dead after DFT
    __shared__ __align__(16) char pool[50688]; // ph1: sx2|sAD4a|sAD4b; ph2: sY
    __shared__ float smu[64];

    float*  sx0   = (float*)pool;                            // 8192 B
    float*  sx1   = (float*)(pool + 8192);                   // 8192 B
    float4* sAD4a = (float4*)(pool + 16384);                 // 32*33*16 = 16896 B
    float4* sAD4b = (float4*)(pool + 33280);                 // 16896 B
    float2* sY    = (float2*)pool;                           // 32240 B (phase 2)
    float*  scoh  = (float*)sTab;                            // 8320 B (phase 2)
    float*  spyy  = (float*)sTab + TN * 1040;                // 520 B

    // ---- stage table ----
    for (int i = tid; i < NF * TABW / 2; i += 256)
        ((float4*)sTab)[i] = ((const float4*)g_tab)[i];

    // ---- load BOTH rows up front (overlapped LDG) ----
    {
        const float4* s0 = (const float4*)(db + ((size_t)b * NDB + n0) * LEN);
        const float4* s1 = (const float4*)(db + ((size_t)b * NDB + n0 + 1) * LEN);
        for (int i = tid; i < LEN / 4; i += 256) {
            ((float4*)sx0)[i] = s0[i];
            ((float4*)sx1)[i] = s1[i];
        }
    }
    __syncthreads();

    // ---- segment means, both rows (float4, ascending adds) ----
    if (tid < 64) {
        int r = tid >> 5, s = tid & 31;
        float acc = 0.f;
        if (s < NSEG) {
            const float4* p = (const float4*)&(r == 0 ? sx0 : sx1)[s * STEP];
            #pragma unroll 4
            for (int t = 0; t < NPS / 4; t++) {
                float4 v = p[t];
                acc += v.x; acc += v.y; acc += v.z; acc += v.w;
            }
        }
        smu[tid] = acc * (1.f / NPS);
    }
    __syncthreads();

    // ---- fold both rows: float4 (A,D @ 2u, A,D @ 2u+1), stride 33/seg ----
    for (int i = tid; i < 2 * 32 * 33; i += 256) {
        int r = i / 1056;
        int rem = i % 1056;
        int s = rem / 33, u = rem % 33;
        float4 v = make_float4(0.f, 0.f, 0.f, 0.f);
        if (s < NSEG) {
            const float* fr = &(r == 0 ? sx0 : sx1)[s * STEP];
            float mu = smu[r * 32 + s];
            int t0 = 2 * u;                    // even: 0..64
            if (t0 == 0)       { v.x = fr[0]  - mu; }
            else if (t0 == 64) { v.x = fr[64] - mu; }
            else {
                float x1 = fr[t0], x2 = fr[128 - t0];
                v.x = (x1 - mu) + (x2 - mu);
                v.y = x1 - x2;
            }
            int t1 = t0 + 1;                   // odd: 1..63 valid, 65 -> zeros
            if (t1 <= 63) {
                float x1 = fr[t1], x2 = fr[128 - t1];
                v.z = (x1 - mu) + (x2 - mu);
                v.w = x1 - x2;
            }
        }
        (r == 0 ? sAD4a : sAD4b)[s * 33 + u] = v;
    }
    __syncthreads();

    // ---- fused DFT: warp w -> freqs [8w,8w+8) (+f=64 on w0); lane=segment --
    {
        int w = tid >> 5, lane = tid & 31;
        const ulonglong2* apA = (const ulonglong2*)(sAD4a + lane * 33);
        const ulonglong2* apB = (const ulonglong2*)(sAD4b + lane * 33);
        int f0 = w * 8;
        ull accA[8] = {0,0,0,0,0,0,0,0};
        ull accB[8] = {0,0,0,0,0,0,0,0};
        ull accA64 = 0, accB64 = 0;
        #pragma unroll 4
        for (int u = 0; u < 32; u++) {
            ulonglong2 adA = apA[u];           // .x=(A,D)@2u  .y=(A,D)@2u+1
            ulonglong2 adB = apB[u];
            DFT_STEP(2 * u,     adA.x, adB.x);
            DFT_STEP(2 * u + 1, adA.y, adB.y);
        }
        {                                       // tail t=64
            ulonglong2 adA = apA[32];
            ulonglong2 adB = apB[32];
            DFT_STEP(64, adA.x, adB.x);
        }
        __syncthreads();                       // sAD dead before sY overlay
        if (lane < NSEG) {
            float2* dA = &sY[0 * NSEG * NF + lane * NF];
            float2* dB = &sY[1 * NSEG * NF + lane * NF];
            #pragma unroll
            for (int j = 0; j < 8; j++) {
                uint32 lo, hi;
                UNPACK2(lo, hi, accA[j]);
                dA[f0 + j] = make_float2(__uint_as_float(lo), __uint_as_float(hi));
                UNPACK2(lo, hi, accB[j]);
                dB[f0 + j] = make_float2(__uint_as_float(lo), __uint_as_float(hi));
            }
            if (w == 0) {
                uint32 lo, hi;
                UNPACK2(lo, hi, accA64);
                dA[64] = make_float2(__uint_as_float(lo), __uint_as_float(hi));
                UNPACK2(lo, hi, accB64);
                dB[64] = make_float2(__uint_as_float(lo), __uint_as_float(hi));
            }
        }
    }
    __syncthreads();

    // ---- Pyy for both rows (ascending s) ----
    for (int it = tid; it < TN * NF; it += 256) {
        int r = it / NF, f = it % NF;
        const float2* Yp = &sY[r * NSEG * NF + f];
        float acc = 0.f;
        #pragma unroll 4
        for (int s = 0; s < NSEG; s++) {
            float2 y = Yp[s * NF];
            acc = fmaf(y.x, y.x, fmaf(y.y, y.y, acc));
        }
        spyy[it] = acc * (1.f / NSEG);
    }
    __syncthreads();

    // ---- Pxy + coherence: thread = (cg, f); Y shared across 4 c's ----
    for (int item = tid; item < 4 * NF; item += 256) {
        int cg = item / NF;                    // c group: c = cg*4 + j
        int f = item % NF;
        const float2* Y0 = &sY[0 * NSEG * NF + f];
        const float2* Y1 = &sY[1 * NSEG * NF + f];
        const float2* Xp[4];
        #pragma unroll
        for (int j = 0; j < 4; j++)
            Xp[j] = g_X + ((size_t)(b * CT + cg * 4 + j)) * (NSEG * NF) + f;
        float pr[4][2], pi[4][2];
        #pragma unroll
        for (int j = 0; j < 4; j++) {
            pr[j][0] = 0.f; pi[j][0] = 0.f;
            pr[j][1] = 0.f; pi[j][1] = 0.f;
        }
        #pragma unroll
        for (int sb = 0; sb < 32; sb += 2) {
            float2 xv[2][4];
            float2 yv[2][2];
            #pragma unroll
            for (int k = 0; k < 2; k++) {
                int s = sb + k;
                if (s < NSEG) {
                    #pragma unroll
                    for (int j = 0; j < 4; j++) xv[k][j] = __ldg(&Xp[j][s * NF]);
                    yv[k][0] = Y0[s * NF];
                    yv[k][1] = Y1[s * NF];
                }
            }
            #pragma unroll
            for (int k = 0; k < 2; k++) {
                int s = sb + k;
                if (s < NSEG) {
                    #pragma unroll
                    for (int j = 0; j < 4; j++) {
                        float2 x = xv[k][j];
                        float2 y0 = yv[k][0];
                        float2 y1 = yv[k][1];
                        pr[j][0] = fmaf(x.x, y0.x, fmaf(x.y, y0.y, pr[j][0]));
                        pi[j][0] = fmaf(x.y, y0.x, fmaf(-x.x, y0.y, pi[j][0]));
                        pr[j][1] = fmaf(x.x, y1.x, fmaf(x.y, y1.y, pr[j][1]));
                        pi[j][1] = fmaf(x.y, y1.x, fmaf(-x.x, y1.y, pi[j][1]));
                    }
                }
            }
        }
        float py0 = spyy[0 * NF + f];
        float py1 = spyy[1 * NF + f];
        #pragma unroll
        for (int j = 0; j < 4; j++) {
            int c = cg * 4 + j;
            float pxx = g_Pxx[(b * CT + c) * NF + f];
            float r0 = pr[j][0] * (1.f / NSEG), i0 = pi[j][0] * (1.f / NSEG);
            float r1 = pr[j][1] * (1.f / NSEG), i1 = pi[j][1] * (1.f / NSEG);
            scoh[0 * 1040 + c * NF + f] = fmaf(r0, r0, i0 * i0) / fmaf(pxx, py0, EPSV);
            scoh[1 * 1040 + c * NF + f] = fmaf(r1, r1, i1 * i1) / fmaf(pxx, py1, EPSV);
        }
    }
    __syncthreads();

    // ---- scores: ascending-f sums ----
    if (tid < CT * TN) {
        int c = tid & (CT - 1), r = tid >> 4;
        const float* p = &scoh[r * 1040 + c * NF];
        float acc = 0.f;
        for (int f = 0; f < NF; f++) acc += p[f];
        g_scores[(size_t)(b * CT + c) * NDB + n0 + r] = acc * (1.f / NF);
    }
}

// ---------------- kernel 3a: top-32 selection (one warp per (b,c)) ---------
__global__ __launch_bounds__(32) void k_sel() {
    int bc = blockIdx.x;
    int lane = threadIdx.x;
    __shared__ float ss[NDB];

    for (int i = lane; i < NDB; i += 32) ss[i] = g_scores[(size_t)bc * NDB + i];
    __syncwarp();

    for (int k = 0; k < TOPK; k++) {
        float bv = -3.402823466e+38f;
        int bi = NDB;
        for (int i = lane; i < NDB; i += 32) {
            float v = ss[i];
            if (v > bv) { bv = v; bi = i; }   // ascending scan: lowest idx on tie
        }
        #pragma unroll
        for (int ofs = 16; ofs > 0; ofs >>= 1) {
            float ov = __shfl_down_sync(0xffffffffu, bv, ofs);
            int   oi = __shfl_down_sync(0xffffffffu, bi, ofs);
            if (ov > bv || (ov == bv && oi < bi)) { bv = ov; bi = oi; }
        }
        bi = __shfl_sync(0xffffffffu, bi, 0);
        if (lane == 0) g_sidx[bc * TOPK + k] = bi;
        ss[bi] = -3.402823466e+38f;            // all lanes, same value
        __syncwarp();
    }
}

// ---------------- kernel 3b: gather (one block per (b,c,k)) ----------------
__global__ __launch_bounds__(256) void k_gather(const float* __restrict__ db,
                                                float* __restrict__ out) {
    int g = blockIdx.x;
    int bc = g / TOPK;
    int b = bc / CT;
    int row = g_sidx[g];
    const float4* src = (const float4*)(db + ((size_t)b * NDB + row) * LEN);
    float4* dst = (float4*)(out + (size_t)g * LEN);
    int tid = threadIdx.x;
    dst[tid] = src[tid];
    dst[tid + 256] = src[tid + 256];
}

// ---------------- launch ----------------------------------------------------
extern "C" void kernel_launch(void* const* d_in, const int* in_sizes, int n_in,
                              void* d_out, int out_size) {
    const float* tgt = (const float*)d_in[0];
    const float* db  = (const float*)d_in[1];
    if (n_in >= 2 && in_sizes[0] > in_sizes[1]) {
        tgt = (const float*)d_in[1];
        db  = (const float*)d_in[0];
    }
    float* out = (float*)d_out;

    int half = BATCH * (NDB / TN) / 2;         // 4096 blocks per half
    k_table<<<(NF * TABW + 255) / 256, 256>>>();
    k_xspec<<<BATCH * CT, 256>>>(tgt);
    k_scores<<<half, 256>>>(db, 0);
    k_scores<<<half, 256>>>(db, half);         // profiler slot
    k_sel<<<BATCH * CT, 32>>>();
    k_gather<<<BATCH * CT * TOPK, 256>>>(db, out);
}

// round 17
// speedup vs baseline: 1.3100x; 1.3100x over previous
#include <cuda_runtime.h>
#include <cuda_bf16.h>
#include <math.h>

#define BATCH 8
#define CT 16
#define LEN 2048
#define NDB 2048
#define NSEG 31
#define NPS 128
#define STEP 64
#define NF 65
#define TABW 66            // table row stride in float2 (16B-aligned rows)
#define TOPK 32
#define TN 2               // DB rows per k_scores block (fused in one t-loop)
#define EPSV 1e-12f
#define PI_D 3.14159265358979323846264338327950288

typedef unsigned long long ull;
typedef unsigned int uint32;

#define FMA2(acc, a, b) asm("fma.rn.f32x2 %0, %1, %2, %0;" : "+l"(acc) : "l"(a), "l"(b))
#define UNPACK2(lo, hi, src) asm("mov.b64 {%0,%1}, %2;" : "=r"(lo), "=r"(hi) : "l"(src))

// ---------------- scratch (__device__ globals; no allocation allowed) ------
__device__ float2 g_tab[NF * TABW];                // [t*TABW+f]: {w*cos, -w*sin}
__device__ float2 g_X[BATCH * CT * NSEG * NF];     // target spectra
__device__ float  g_Pxx[BATCH * CT * NF];
__device__ float  g_scores[BATCH * CT * NDB];
__device__ int    g_sidx[BATCH * CT * TOPK];

// ---------------- kernel 0: half twiddle table (Hann folded, double prec) --
__global__ void k_table() {
    int i = blockIdx.x * blockDim.x + threadIdx.x;
    if (i < NF * TABW) {
        int t = i / TABW, f = i % TABW;
        if (f < NF) {
            double w = 0.5 - 0.5 * cos(2.0 * PI_D * (double)t / (double)NPS);
            double ang = 2.0 * PI_D * (double)f * (double)t / (double)NPS;
            float ws = (t == 0 || t == 64) ? 0.f : (float)(-w * sin(ang));
            g_tab[i] = make_float2((float)(w * cos(ang)), ws);
        } else {
            g_tab[i] = make_float2(0.f, 0.f);
        }
    }
}

// ---------------- kernel 1: X spectra + Pxx (one block per (b,c)) ----------
// Same numerics as R15 (bit-identical); only change: g_tab staged to smem so
// the per-thread DFT reads LDS instead of scattered global loads.
__global__ __launch_bounds__(256) void k_xspec(const float* __restrict__ tgt) {
    int bc = blockIdx.x;
    int tid = threadIdx.x;
    __shared__ float2 sTab[NF * TABW];
    __shared__ float sx[2176];
    __shared__ float smu[32];
    __shared__ float2 sY[NSEG * NF];

    for (int i = tid; i < NF * TABW / 2; i += 256)
        ((float4*)sTab)[i] = ((const float4*)g_tab)[i];

    const float* src = tgt + (size_t)bc * LEN;
    for (int i = tid; i < LEN; i += 256) sx[i] = src[i];
    for (int i = LEN + tid; i < 2176; i += 256) sx[i] = 0.f;
    __syncthreads();
    if (tid < 32) {
        float acc = 0.f;
        if (tid < NSEG) {
            const float* p = &sx[tid * STEP];
            for (int t = 0; t < NPS; t++) acc += p[t];
        }
        smu[tid] = acc * (1.f / NPS);
    }
    __syncthreads();
    for (int o = tid; o < NSEG * NF; o += 256) {
        int s = o / NF, f = o % NF;
        const float* fr = &sx[s * STEP];
        float mu = smu[s];
        float ar = 0.f, ai = 0.f;
        {
            float v0 = fr[0] - mu;
            float2 tb = sTab[f];                  // t=0
            ar = fmaf(v0, tb.x, ar);
        }
        for (int t = 1; t < 64; t++) {
            float a = (fr[t] - mu) + (fr[128 - t] - mu);
            float d = fr[t] - fr[128 - t];
            float2 tb = sTab[t * TABW + f];
            ar = fmaf(a, tb.x, ar);
            ai = fmaf(d, tb.y, ai);
        }
        {
            float v64 = fr[64] - mu;
            float2 tb = sTab[64 * TABW + f];
            ar = fmaf(v64, tb.x, ar);
        }
        sY[o] = make_float2(ar, ai);
        g_X[(size_t)bc * (NSEG * NF) + o] = make_float2(ar, ai);
    }
    __syncthreads();
    if (tid < NF) {
        float acc = 0.f;
        for (int s = 0; s < NSEG; s++) {
            float2 y = sY[s * NF + tid];
            acc = fmaf(y.x, y.x, fmaf(y.y, y.y, acc));
        }
        g_Pxx[bc * NF + tid] = acc * (1.f / NSEG);
    }
}

// ---------------- kernel 2: scores (one block per TN=2 DB rows) ------------
// Exact R15 kernel (known 676 us, rel_err 0.0): fused 2-row DFT with stride-67
// LDS.64 AD loads; Pxy thread = (cg, f), Y shared across 4 c's, X batched.
__global__ __launch_bounds__(256, 2) void k_scores(const float* __restrict__ db,
                                                   int blk_base) {
    int blk = blk_base + blockIdx.x;           // b * (NDB/TN) + ntile
    int b = blk / (NDB / TN);
    int n0 = (blk % (NDB / TN)) * TN;
    int tid = threadIdx.x;

    __shared__ float2 sTab[NF * TABW];         // 34320 B; dead after DFT
    __shared__ __align__(16) char pool[50688]; // ph1: sx2|sADa|sADb; ph2: sY
    __shared__ float smu[64];

    float*  sx0  = (float*)pool;                             // 8192 B
    float*  sx1  = (float*)(pool + 8192);                    // 8192 B
    float2* sADa = (float2*)(pool + 16384);                  // 17152 B
    float2* sADb = (float2*)(pool + 33536);                  // 17152 B
    float2* sY   = (float2*)pool;                            // 32240 B (phase 2)
    float*  scoh = (float*)sTab;                             // 8320 B (phase 2)
    float*  spyy = (float*)sTab + TN * 1040;                 // 520 B

    // ---- stage table ----
    for (int i = tid; i < NF * TABW / 2; i += 256)
        ((float4*)sTab)[i] = ((const float4*)g_tab)[i];

    // ---- load BOTH rows up front (overlapped LDG) ----
    {
        const float4* s0 = (const float4*)(db + ((size_t)b * NDB + n0) * LEN);
        const float4* s1 = (const float4*)(db + ((size_t)b * NDB + n0 + 1) * LEN);
        for (int i = tid; i < LEN / 4; i += 256) {
            ((float4*)sx0)[i] = s0[i];
            ((float4*)sx1)[i] = s1[i];
        }
    }
    __syncthreads();

    // ---- segment means, both rows (float4, ascending adds) ----
    if (tid < 64) {
        int r = tid >> 5, s = tid & 31;
        float acc = 0.f;
        if (s < NSEG) {
            const float4* p = (const float4*)&(r == 0 ? sx0 : sx1)[s * STEP];
            #pragma unroll 4
            for (int t = 0; t < NPS / 4; t++) {
                float4 v = p[t];
                acc += v.x; acc += v.y; acc += v.z; acc += v.w;
            }
        }
        smu[tid] = acc * (1.f / NPS);
    }
    __syncthreads();

    // ---- fold both rows: (A,D) interleaved, stride 67 ----
    for (int i = tid; i < 2 * 32 * 65; i += 256) {
        int r = i / 2080;
        int rem = i % 2080;
        int s = rem / 65, t = rem % 65;
        float2* AD = r == 0 ? sADa : sADb;
        if (s < NSEG) {
            const float* fr = &(r == 0 ? sx0 : sx1)[s * STEP];
            float mu = smu[r * 32 + s];
            float A, D;
            if (t == 0)       { A = fr[0]  - mu; D = 0.f; }
            else if (t == 64) { A = fr[64] - mu; D = 0.f; }
            else {
                float x1 = fr[t], x2 = fr[128 - t];
                A = (x1 - mu) + (x2 - mu);
                D = x1 - x2;
            }
            AD[s * 67 + t] = make_float2(A, D);
        } else {
            AD[s * 67 + t] = make_float2(0.f, 0.f);
        }
    }
    __syncthreads();

    // ---- fused DFT: warp w -> freqs [8w,8w+8) (+f=64 on w0); lane=segment --
    {
        int w = tid >> 5, lane = tid & 31;
        const float2* adpA = &sADa[lane * 67];
        const float2* adpB = &sADb[lane * 67];
        int f0 = w * 8;
        ull accA[8] = {0,0,0,0,0,0,0,0};
        ull accB[8] = {0,0,0,0,0,0,0,0};
        ull accA64 = 0, accB64 = 0;
        #pragma unroll 13
        for (int t = 0; t <= 64; t++) {
            ull adA = *(const ull*)&adpA[t];               // LDS.64 (A,D) row0
            ull adB = *(const ull*)&adpB[t];               // LDS.64 (A,D) row1
            const ulonglong2* tq = (const ulonglong2*)&sTab[t * TABW + f0];
            ulonglong2 q0 = tq[0];
            ulonglong2 q1 = tq[1];
            ulonglong2 q2 = tq[2];
            ulonglong2 q3 = tq[3];
            FMA2(accA[0], adA, q0.x); FMA2(accB[0], adB, q0.x);
            FMA2(accA[1], adA, q0.y); FMA2(accB[1], adB, q0.y);
            FMA2(accA[2], adA, q1.x); FMA2(accB[2], adB, q1.x);
            FMA2(accA[3], adA, q1.y); FMA2(accB[3], adB, q1.y);
            FMA2(accA[4], adA, q2.x); FMA2(accB[4], adB, q2.x);
            FMA2(accA[5], adA, q2.y); FMA2(accB[5], adB, q2.y);
            FMA2(accA[6], adA, q3.x); FMA2(accB[6], adB, q3.x);
            FMA2(accA[7], adA, q3.y); FMA2(accB[7], adB, q3.y);
            if (w == 0) {
                ull t64 = *(const ull*)&sTab[t * TABW + 64];
                FMA2(accA64, adA, t64);
                FMA2(accB64, adB, t64);
            }
        }
        __syncthreads();                       // sAD dead before sY overlay
        if (lane < NSEG) {
            float2* dA = &sY[0 * NSEG * NF + lane * NF];
            float2* dB = &sY[1 * NSEG * NF + lane * NF];
            #pragma unroll
            for (int j = 0; j < 8; j++) {
                uint32 lo, hi;
                UNPACK2(lo, hi, accA[j]);
                dA[f0 + j] = make_float2(__uint_as_float(lo), __uint_as_float(hi));
                UNPACK2(lo, hi, accB[j]);
                dB[f0 + j] = make_float2(__uint_as_float(lo), __uint_as_float(hi));
            }
            if (w == 0) {
                uint32 lo, hi;
                UNPACK2(lo, hi, accA64);
                dA[64] = make_float2(__uint_as_float(lo), __uint_as_float(hi));
                UNPACK2(lo, hi, accB64);
                dB[64] = make_float2(__uint_as_float(lo), __uint_as_float(hi));
            }
        }
    }
    __syncthreads();

    // ---- Pyy for both rows (ascending s) ----
    for (int it = tid; it < TN * NF; it += 256) {
        int r = it / NF, f = it % NF;
        const float2* Yp = &sY[r * NSEG * NF + f];
        float acc = 0.f;
        #pragma unroll 4
        for (int s = 0; s < NSEG; s++) {
            float2 y = Yp[s * NF];
            acc = fmaf(y.x, y.x, fmaf(y.y, y.y, acc));
        }
        spyy[it] = acc * (1.f / NSEG);
    }
    __syncthreads();

    // ---- Pxy + coherence: thread = (cg, f); Y shared across 4 c's ----
    for (int item = tid; item < 4 * NF; item += 256) {
        int cg = item / NF;                    // c group: c = cg*4 + j
        int f = item % NF;
        const float2* Y0 = &sY[0 * NSEG * NF + f];
        const float2* Y1 = &sY[1 * NSEG * NF + f];
        const float2* Xp[4];
        #pragma unroll
        for (int j = 0; j < 4; j++)
            Xp[j] = g_X + ((size_t)(b * CT + cg * 4 + j)) * (NSEG * NF) + f;
        float pr[4][2], pi[4][2];
        #pragma unroll
        for (int j = 0; j < 4; j++) {
            pr[j][0] = 0.f; pi[j][0] = 0.f;
            pr[j][1] = 0.f; pi[j][1] = 0.f;
        }
        #pragma unroll
        for (int sb = 0; sb < 32; sb += 2) {
            float2 xv[2][4];
            float2 yv[2][2];
            #pragma unroll
            for (int k = 0; k < 2; k++) {
                int s = sb + k;
                if (s < NSEG) {
                    #pragma unroll
                    for (int j = 0; j < 4; j++) xv[k][j] = __ldg(&Xp[j][s * NF]);
                    yv[k][0] = Y0[s * NF];
                    yv[k][1] = Y1[s * NF];
                }
            }
            #pragma unroll
            for (int k = 0; k < 2; k++) {
                int s = sb + k;
                if (s < NSEG) {
                    #pragma unroll
                    for (int j = 0; j < 4; j++) {
                        float2 x = xv[k][j];
                        float2 y0 = yv[k][0];
                        float2 y1 = yv[k][1];
                        pr[j][0] = fmaf(x.x, y0.x, fmaf(x.y, y0.y, pr[j][0]));
                        pi[j][0] = fmaf(x.y, y0.x, fmaf(-x.x, y0.y, pi[j][0]));
                        pr[j][1] = fmaf(x.x, y1.x, fmaf(x.y, y1.y, pr[j][1]));
                        pi[j][1] = fmaf(x.y, y1.x, fmaf(-x.x, y1.y, pi[j][1]));
                    }
                }
            }
        }
        float py0 = spyy[0 * NF + f];
        float py1 = spyy[1 * NF + f];
        #pragma unroll
        for (int j = 0; j < 4; j++) {
            int c = cg * 4 + j;
            float pxx = g_Pxx[(b * CT + c) * NF + f];
            float r0 = pr[j][0] * (1.f / NSEG), i0 = pi[j][0] * (1.f / NSEG);
            float r1 = pr[j][1] * (1.f / NSEG), i1 = pi[j][1] * (1.f / NSEG);
            scoh[0 * 1040 + c * NF + f] = fmaf(r0, r0, i0 * i0) / fmaf(pxx, py0, EPSV);
            scoh[1 * 1040 + c * NF + f] = fmaf(r1, r1, i1 * i1) / fmaf(pxx, py1, EPSV);
        }
    }
    __syncthreads();

    // ---- scores: ascending-f sums ----
    if (tid < CT * TN) {
        int c = tid & (CT - 1), r = tid >> 4;
        const float* p = &scoh[r * 1040 + c * NF];
        float acc = 0.f;
        for (int f = 0; f < NF; f++) acc += p[f];
        g_scores[(size_t)(b * CT + c) * NDB + n0 + r] = acc * (1.f / NF);
    }
}

// ---------------- kernel 3a: top-32 selection (one warp per (b,c)) ---------
__global__ __launch_bounds__(32) void k_sel() {
    int bc = blockIdx.x;
    int lane = threadIdx.x;
    __shared__ float ss[NDB];

    for (int i = lane; i < NDB; i += 32) ss[i] = g_scores[(size_t)bc * NDB + i];
    __syncwarp();

    for (int k = 0; k < TOPK; k++) {
        float bv = -3.402823466e+38f;
        int bi = NDB;
        for (int i = lane; i < NDB; i += 32) {
            float v = ss[i];
            if (v > bv) { bv = v; bi = i; }   // ascending scan: lowest idx on tie
        }
        #pragma unroll
        for (int ofs = 16; ofs > 0; ofs >>= 1) {
            float ov = __shfl_down_sync(0xffffffffu, bv, ofs);
            int   oi = __shfl_down_sync(0xffffffffu, bi, ofs);
            if (ov > bv || (ov == bv && oi < bi)) { bv = ov; bi = oi; }
        }
        bi = __shfl_sync(0xffffffffu, bi, 0);
        if (lane == 0) g_sidx[bc * TOPK + k] = bi;
        ss[bi] = -3.402823466e+38f;            // all lanes, same value
        __syncwarp();
    }
}

// ---------------- kernel 3b: gather (one block per (b,c,k)) ----------------
__global__ __launch_bounds__(256) void k_gather(const float* __restrict__ db,
                                                float* __restrict__ out) {
    int g = blockIdx.x;
    int bc = g / TOPK;
    int b = bc / CT;
    int row = g_sidx[g];
    const float4* src = (const float4*)(db + ((size_t)b * NDB + row) * LEN);
    float4* dst = (float4*)(out + (size_t)g * LEN);
    int tid = threadIdx.x;
    dst[tid] = src[tid];
    dst[tid + 256] = src[tid + 256];
}

// ---------------- launch ----------------------------------------------------
extern "C" void kernel_launch(void* const* d_in, const int* in_sizes, int n_in,
                              void* d_out, int out_size) {
    const float* tgt = (const float*)d_in[0];
    const float* db  = (const float*)d_in[1];
    if (n_in >= 2 && in_sizes[0] > in_sizes[1]) {
        tgt = (const float*)d_in[1];
        db  = (const float*)d_in[0];
    }
    float* out = (float*)d_out;

    int half = BATCH * (NDB / TN) / 2;         // 4096 blocks per half
    k_table<<<(NF * TABW + 255) / 256, 256>>>();
    k_xspec<<<BATCH * CT, 256>>>(tgt);
    k_scores<<<half, 256>>>(db, 0);
    k_scores<<<half, 256>>>(db, half);         // profiler slot
    k_sel<<<BATCH * CT, 32>>>();
    k_gather<<<BATCH * CT * TOPK, 256>>>(db, out);
}